// round 7
// baseline (speedup 1.0000x reference)
#include <cuda_runtime.h>
#include <cuda_bf16.h>

#define B_    32
#define C_    768
#define CR_   192
#define BC_   24576            // B*C channels
#define BCR_  6144             // B*Cr
#define NCTA  148              // 1 CTA/SM -> co-residency guaranteed
#define NWARP (NCTA * 8)       // 1184
#define MAXCH 21               // ceil(BC_/NWARP)
#define STASH 6                // channels stashed in smem per warp
#define SMEM_BYTES (8 * STASH * 4096)   // 196608 B dynamic smem

// Scratch + barrier state (all zero-init; barrier returns to zero each launch)
__device__ float d_s[BC_];
__device__ float d_h[BCR_];
__device__ unsigned bar_cnt;
__device__ unsigned bar_sense;

// Sense-reversing grid barrier. Exactly two uses per launch (targets 1 then 0)
// so bar_sense ends at 0 and bar_cnt at 0 -> clean across graph replays.
__device__ __forceinline__ void grid_bar(unsigned target) {
    __syncthreads();
    if (threadIdx.x == 0) {
        __threadfence();
        if (atomicAdd(&bar_cnt, 1) == NCTA - 1) {
            atomicExch(&bar_cnt, 0);
            __threadfence();
            atomicExch(&bar_sense, target);
        } else {
            while (atomicAdd(&bar_sense, 0) != target) {}
        }
    }
    __syncthreads();
}

extern __shared__ float4 stash_sm[];   // [8*STASH][256] float4

__global__ __launch_bounds__(256) void se_kernel(const float* __restrict__ x,
                                                 const float* __restrict__ w1,
                                                 const float* __restrict__ b1,
                                                 const float* __restrict__ w2,
                                                 const float* __restrict__ b2,
                                                 float* __restrict__ out) {
    int tid  = threadIdx.x;
    int warp = tid >> 5;
    int lane = tid & 31;
    int gw   = blockIdx.x * 8 + warp;          // 0..1183
    __shared__ float gates_sm[8][MAXCH];

    // ---------------- Phase 1: pool (+ smem stash of first STASH channels) --
    {
        int i = 0;
        for (int ch = gw; ch < BC_; ch += NWARP, i++) {
            const float4* p = reinterpret_cast<const float4*>(x) + (size_t)ch * 256;
            float sum = 0.0f;
            if (i < STASH) {
                int s = warp * STASH + i;
                float4 v[8];
#pragma unroll
                for (int j = 0; j < 8; j++) v[j] = __ldcs(p + lane + j * 32);
#pragma unroll
                for (int j = 0; j < 8; j++) {
                    stash_sm[s * 256 + lane + j * 32] = v[j];
                    sum += (v[j].x + v[j].y) + (v[j].z + v[j].w);
                }
            } else {
                float4 v[8];
#pragma unroll
                for (int j = 0; j < 8; j++) v[j] = p[lane + j * 32];
#pragma unroll
                for (int j = 0; j < 8; j++)
                    sum += (v[j].x + v[j].y) + (v[j].z + v[j].w);
            }
#pragma unroll
            for (int o = 16; o; o >>= 1) sum += __shfl_xor_sync(0xffffffffu, sum, o);
            if (lane == 0) d_s[ch] = sum * (1.0f / 1024.0f);
        }
    }
    grid_bar(1);

    // ---------------- Phase 2: h = swish(s @ w1^T + b1), warp per dot -------
    for (int j = gw; j < BCR_; j += NWARP) {
        int o  = j % CR_;
        int b  = j / CR_;
        const float* wr = w1 + (size_t)o * C_;
        const float* sr = d_s + b * C_;
        float acc = 0.0f;
#pragma unroll
        for (int t = 0; t < C_ / 32; t++) {
            int k = lane + t * 32;
            acc += sr[k] * wr[k];
        }
#pragma unroll
        for (int q = 16; q; q >>= 1) acc += __shfl_xor_sync(0xffffffffu, acc, q);
        if (lane == 0) {
            float h = acc + b1[o];
            d_h[b * CR_ + o] = h / (1.0f + __expf(-h));
        }
    }
    grid_bar(0);

    // ---------------- Phase 3a: gates, lane-parallel (lane i -> channel i) --
    {
        int ch = gw + lane * NWARP;
        if (lane < MAXCH && ch < BC_) {
            int b = ch / C_;
            int c = ch % C_;
            const float4* h4 = reinterpret_cast<const float4*>(d_h + b * CR_);
            const float4* w4 = reinterpret_cast<const float4*>(w2 + (size_t)c * CR_);
            float acc = 0.0f;
#pragma unroll
            for (int k = 0; k < CR_ / 4; k++) {
                float4 a = h4[k], w = w4[k];
                acc += (a.x * w.x + a.y * w.y) + (a.z * w.z + a.w * w.w);
            }
            gates_sm[warp][lane] = 1.0f / (1.0f + __expf(-(acc + b2[c])));
        }
        __syncwarp();
    }

    // ---------------- Phase 3b: out = x * g ---------------------------------
    {
        int i = 0;
        for (int ch = gw; ch < BC_; ch += NWARP, i++) {
            float g = gates_sm[warp][i];
            float4* o4 = reinterpret_cast<float4*>(out) + (size_t)ch * 256;
            if (i < STASH) {
                int s = warp * STASH + i;
#pragma unroll
                for (int j = 0; j < 8; j++) {
                    float4 v = stash_sm[s * 256 + lane + j * 32];
                    v.x *= g; v.y *= g; v.z *= g; v.w *= g;
                    __stcs(o4 + lane + j * 32, v);
                }
            } else {
                const float4* p = reinterpret_cast<const float4*>(x) + (size_t)ch * 256;
                float4 v[8];
#pragma unroll
                for (int j = 0; j < 8; j++) v[j] = __ldcs(p + lane + j * 32);
#pragma unroll
                for (int j = 0; j < 8; j++) {
                    v[j].x *= g; v[j].y *= g; v[j].z *= g; v[j].w *= g;
                    __stcs(o4 + lane + j * 32, v[j]);
                }
            }
        }
    }
}

// ---------------------------------------------------------------------------
extern "C" void kernel_launch(void* const* d_in, const int* in_sizes, int n_in,
                              void* d_out, int out_size) {
    const float* x  = (const float*)d_in[0];
    const float* w1 = (const float*)d_in[1];
    const float* b1 = (const float*)d_in[2];
    const float* w2 = (const float*)d_in[3];
    const float* b2 = (const float*)d_in[4];
    float* out = (float*)d_out;

    cudaFuncSetAttribute(se_kernel, cudaFuncAttributeMaxDynamicSharedMemorySize,
                         SMEM_BYTES);
    se_kernel<<<NCTA, 256, SMEM_BYTES>>>(x, w1, b1, w2, b2, out);
}

// round 8
// speedup vs baseline: 1.1230x; 1.1230x over previous
#include <cuda_runtime.h>
#include <cuda_bf16.h>

#define B_    32
#define C_    768
#define CR_   192
#define BC_   24576            // B*C channels
#define BCR_  6144             // B*Cr
#define NCTA  148              // 1 CTA/SM
#define WPB   32               // warps per CTA (1024 threads)
#define NWARP (NCTA * WPB)     // 4736
#define MAXCH 6                // ceil(BC_/NWARP) = 5.19 -> 6
#define SMEM_BYTES (WPB * 4096)   // 131072 B: 1 stashed channel per warp

// Scratch + barrier state (zero-init; barrier returns to zero each launch)
__device__ float d_s[BC_];
__device__ float d_h[BCR_];
__device__ unsigned bar_cnt;
__device__ unsigned bar_sense;

// Sense-reversing grid barrier; used exactly twice (targets 1 then 0) so all
// state ends at zero -> safe across CUDA-graph replays.
__device__ __forceinline__ void grid_bar(unsigned target) {
    __syncthreads();
    if (threadIdx.x == 0) {
        __threadfence();
        if (atomicAdd(&bar_cnt, 1) == NCTA - 1) {
            atomicExch(&bar_cnt, 0);
            __threadfence();
            atomicExch(&bar_sense, target);
        } else {
            while (atomicAdd(&bar_sense, 0) != target) {}
        }
    }
    __syncthreads();
}

extern __shared__ float4 stash_sm[];   // [WPB][256] float4 (one channel/warp)

__global__ __launch_bounds__(1024, 1)
void se_kernel(const float* __restrict__ x,
               const float* __restrict__ w1,
               const float* __restrict__ b1,
               const float* __restrict__ w2,
               const float* __restrict__ b2,
               float* __restrict__ out) {
    int tid  = threadIdx.x;
    int warp = tid >> 5;                       // 0..31
    int lane = tid & 31;
    int gw   = blockIdx.x * WPB + warp;        // 0..4735
    __shared__ float gates_sm[WPB][MAXCH];

    // ---------------- Phase 1: pool; stash channel 0 of each warp in smem ---
    {
        int i = 0;
        for (int ch = gw; ch < BC_; ch += NWARP, i++) {
            const float4* p = reinterpret_cast<const float4*>(x) + (size_t)ch * 256;
            float4 v[8];
#pragma unroll
            for (int j = 0; j < 8; j++) v[j] = p[lane + j * 32];
            float sum = 0.0f;
            if (i == 0) {
#pragma unroll
                for (int j = 0; j < 8; j++) {
                    stash_sm[warp * 256 + lane + j * 32] = v[j];
                    sum += (v[j].x + v[j].y) + (v[j].z + v[j].w);
                }
            } else {
#pragma unroll
                for (int j = 0; j < 8; j++)
                    sum += (v[j].x + v[j].y) + (v[j].z + v[j].w);
            }
#pragma unroll
            for (int o = 16; o; o >>= 1) sum += __shfl_xor_sync(0xffffffffu, sum, o);
            if (lane == 0) d_s[ch] = sum * (1.0f / 1024.0f);
        }
    }
    grid_bar(1);

    // ---------------- Phase 2: h = swish(s @ w1^T + b1), warp per dot -------
    for (int j = gw; j < BCR_; j += NWARP) {   // 6144 dots over 4736 warps
        int o  = j % CR_;
        int b  = j / CR_;
        const float* wr = w1 + (size_t)o * C_;
        const float* sr = d_s + b * C_;
        float acc = 0.0f;
#pragma unroll
        for (int t = 0; t < C_ / 32; t++) {
            int k = lane + t * 32;
            acc += sr[k] * wr[k];
        }
#pragma unroll
        for (int q = 16; q; q >>= 1) acc += __shfl_xor_sync(0xffffffffu, acc, q);
        if (lane == 0) {
            float h = acc + b1[o];
            d_h[b * CR_ + o] = h / (1.0f + __expf(-h));
        }
    }
    grid_bar(0);

    // ---------------- Phase 3a: gates, lane-parallel (lane i -> i-th chan) --
    {
        int ch = gw + lane * NWARP;
        if (lane < MAXCH && ch < BC_) {
            int b = ch / C_;
            int c = ch % C_;
            const float4* h4 = reinterpret_cast<const float4*>(d_h + b * CR_);
            const float4* w4 = reinterpret_cast<const float4*>(w2 + (size_t)c * CR_);
            float acc = 0.0f;
#pragma unroll
            for (int k = 0; k < CR_ / 4; k++) {
                float4 a = h4[k], w = w4[k];
                acc += (a.x * w.x + a.y * w.y) + (a.z * w.z + a.w * w.w);
            }
            gates_sm[warp][lane] = 1.0f / (1.0f + __expf(-(acc + b2[c])));
        }
        __syncwarp();
    }

    // ---------------- Phase 3b: out = x * g ---------------------------------
    {
        int i = 0;
        for (int ch = gw; ch < BC_; ch += NWARP, i++) {
            float g = gates_sm[warp][i];
            float4* o4 = reinterpret_cast<float4*>(out) + (size_t)ch * 256;
            if (i == 0) {
#pragma unroll
                for (int j = 0; j < 8; j++) {
                    float4 v = stash_sm[warp * 256 + lane + j * 32];
                    v.x *= g; v.y *= g; v.z *= g; v.w *= g;
                    __stcs(o4 + lane + j * 32, v);
                }
            } else {
                const float4* p = reinterpret_cast<const float4*>(x) + (size_t)ch * 256;
                float4 v[8];
#pragma unroll
                for (int j = 0; j < 8; j++) v[j] = __ldcs(p + lane + j * 32);
#pragma unroll
                for (int j = 0; j < 8; j++) {
                    v[j].x *= g; v[j].y *= g; v[j].z *= g; v[j].w *= g;
                    __stcs(o4 + lane + j * 32, v[j]);
                }
            }
        }
    }
}

// ---------------------------------------------------------------------------
extern "C" void kernel_launch(void* const* d_in, const int* in_sizes, int n_in,
                              void* d_out, int out_size) {
    const float* x  = (const float*)d_in[0];
    const float* w1 = (const float*)d_in[1];
    const float* b1 = (const float*)d_in[2];
    const float* w2 = (const float*)d_in[3];
    const float* b2 = (const float*)d_in[4];
    float* out = (float*)d_out;

    cudaFuncSetAttribute(se_kernel, cudaFuncAttributeMaxDynamicSharedMemorySize,
                         SMEM_BYTES);
    se_kernel<<<NCTA, 1024, SMEM_BYTES>>>(x, w1, b1, w2, b2, out);
}